// round 10
// baseline (speedup 1.0000x reference)
#include <cuda_runtime.h>
#include <cuda_bf16.h>

#define FULL 0xffffffffu
#define NEGV -1000000000.0f

// Problem shape (fixed): B=64, N=128, L=32
#define BB    64
#define NN_   128
#define LL    32
#define NN2   (NN_ * NN_)            /* 16384 cells per batch */
#define CELLS (BB * NN2)             /* 1,048,576 cells        */
#define K1_CPB 256                   /* cells per K1 block (8 warps x 32) */
#define K1_BLOCKS (CELLS / K1_CPB)   /* 4096                   */
#define PARTS (NN2 / K1_CPB)         /* 64 gold partials per batch */
#define TT    8                      /* width-tile size */

#define PA    129                    /* A pitch (odd -> row-per-lane conflict-free) */
#define AROWS 136                    /* A rows incl. NEG pads */
#define PBE   137                    /* Bend pitch (9 mod 32 -> bulk conflict-free) */
#define BEROWS 144                   /* Bend rows incl. NEG pads */
#define PSP   129                    /* potS pitch (odd) */
#define PT    9                      /* Pt pitch */
#define PTROWS 136

// ---------------- device scratch (no allocations allowed) ----------------
__device__ float g_pot[CELLS];            // row-major pot[b][i][j] (upper triangle valid)
__device__ float g_goldpart[BB * PARTS];  // per-block gold partial sums
__device__ float g_margin[BB];
__device__ unsigned g_count;              // wrapping completion counter (replay-safe)

// ---------------- K1: pot (row-major, upper tri only) + gold partials ----------------
// 8 warps x 32 cells. Warp stages 4KB of logits into smem (pitch 33 = conflict-free),
// then each lane processes its own cell: x_g read, slot g := NEG, 31-fmax tree.
//   pot  = max(maxall_excl_g + 1, x_g) - x_0
//   gold = x_g - x_0  (summed warp-wide via fixed shfl tree -> deterministic)
// The -1e9 augment on (b,0,len-1,0) is patched in K2.
__global__ void __launch_bounds__(256) k1_pot(const float* __restrict__ logits,
                                              const void* __restrict__ labels) {
    __shared__ float stage[8][32 * 33];
    __shared__ float gsh[8];
    const int warp = threadIdx.x >> 5;
    const int lane = threadIdx.x & 31;

    // labels dtype detection (uniform, deterministic): int64 values lie in [-100,32)
    long long v0 = ((const long long*)labels)[lane];
    const bool lab64 = (__ballot_sync(FULL, v0 >= -100 && v0 < 32) == FULL);

    const int c0 = (blockIdx.x * 8 + warp) * 32;
    const int c  = c0 + lane;                       // this lane's cell
    int g = lab64 ? (int)((const long long*)labels)[c]
                  : ((const int*)labels)[c];
    if (g < 0) g = 0;

    // stage 32 cells x 32 labels (coalesced LDG.128, conflict-free scalar STS)
    const float4* src = (const float4*)(logits + (size_t)c0 * LL);
    float* sw = stage[warp];
#pragma unroll
    for (int j = 0; j < 8; ++j) {
        float4 f = src[lane + 32 * j];
        int p = lane + 32 * j;                      // float4 index
        int cell = p >> 3, off = (p & 7) << 2;
        float* d = sw + cell * 33 + off;
        d[0] = f.x; d[1] = f.y; d[2] = f.z; d[3] = f.w;
    }
    __syncwarp();

    float* row = sw + lane * 33;
    float xg = row[g];
    float x0 = row[0];
    row[g] = NEGV;                                  // exclude gold label from the max
    float a0 = row[0], a1 = row[1], a2 = row[2], a3 = row[3];
#pragma unroll
    for (int t = 4; t < 32; t += 4) {
        a0 = fmaxf(a0, row[t]);
        a1 = fmaxf(a1, row[t + 1]);
        a2 = fmaxf(a2, row[t + 2]);
        a3 = fmaxf(a3, row[t + 3]);
    }
    float mx = fmaxf(fmaxf(a0, a1), fmaxf(a2, a3));
    float pot = fmaxf(mx + 1.0f, xg) - x0;

    const int ii = (c0 >> 7) & 127;                 // row index (one row per warp)
    const int j  = c & 127;
    if (j >= ii) g_pot[c] = pot;                    // upper triangle only, coalesced

    float gs = xg - x0;                             // gold contribution
#pragma unroll
    for (int o = 16; o; o >>= 1) gs += __shfl_xor_sync(FULL, gs, o);
    if (lane == 0) gsh[warp] = gs;
    __syncthreads();
    if (threadIdx.x == 0) {
        float s = 0.0f;
#pragma unroll
        for (int t = 0; t < 8; ++t) s += gsh[t];    // fixed order -> deterministic
        g_goldpart[blockIdx.x] = s;                 // blockIdx = b*PARTS + local
    }
}

// ---------------- K2: per-batch tiled max-plus CKY (dual-array, 4-warp fixup) ----------------
// A[i][k]   = beta(i, width k)   (start-indexed, pitch 129)
// Bend[j][c]= beta(span ending j, width 127-c)   (end-indexed, pitch 137)
// Bulk (all 16 warps, no syncs): P(i,s) = max_{k=0..W} A[i][k] + Bend[i+W+s][128-W-s+k]
//   lane l = 4*ir+sg, row i = rb*8+ir, acc0 -> s=sg+1, acc1 -> s=sg+5; banks verified.
// Fixup (warps 0-3, one row/lane, serial terms, named barrier per s-step):
//   w = W+s: terms k=t and k=w-1-t for t=0..s-2, all via A (odd pitch -> conflict-free).
__global__ void __launch_bounds__(512) k2_cky(const float* __restrict__ logits,
                                              const void* __restrict__ labels,
                                              float* __restrict__ out) {
    extern __shared__ float smem[];
    float* A    = smem;                              // AROWS * PA
    float* Bend = A + AROWS * PA;                    // BEROWS * PBE
    float* potS = Bend + BEROWS * PBE;               // NN_ * PSP
    float* Pt   = potS + NN_ * PSP;                  // PTROWS * PT
    __shared__ float red[PARTS];

    const int b    = blockIdx.x;
    const int tid  = threadIdx.x;
    const int warp = tid >> 5;
    const int lane = tid & 31;
    const int ir   = lane >> 2;
    const int sg   = lane & 3;
    const int rb   = (warp < 8) ? warp : (23 - warp);   // pair-reversed row blocks
    const int i    = rb * 8 + ir;

    long long v = ((const long long*)labels)[lane];
    const bool lab64 = (__ballot_sync(FULL, v >= -100 && v < 32) == FULL);

    // sequence length = count(labels[b,0,:] != -100)
    int pflag = 0;
    if (tid < NN_) {
        size_t idx = ((size_t)b << 14) + tid;
        int lab = lab64 ? (int)((const long long*)labels)[idx]
                        : ((const int*)labels)[idx];
        pflag = (lab != -100);
    }
    const int len = __syncthreads_count(pflag);

    if (tid < PARTS) red[tid] = g_goldpart[b * PARTS + tid];

    // ---- NEG-init A and Bend (incl. pads) + stage potS[i][w] = pot[i][i+w] ----
    {
        float4* f4 = (float4*)smem;
        const float4 n4 = make_float4(NEGV, NEGV, NEGV, NEGV);
        const int ninit = (AROWS * PA + BEROWS * PBE) / 4;    // 9318
        for (int t = tid; t < ninit; t += 512) f4[t] = n4;
        const float* potb = g_pot + ((size_t)b << 14);
        for (int t = tid; t < NN2; t += 512) {
            int ri = t >> 7, w = t & 127;
            potS[ri * PSP + w] = (ri + w < NN_) ? potb[(ri << 7) + ri + w] : NEGV;
        }
    }
    __syncthreads();

    // ---- patch pot[b,0,len-1] with the extra -1e9 augment on label 0 ----
    if (tid < 32) {
        const int jj = len - 1;
        size_t cell = ((size_t)b << 14) + jj;
        int g = lab64 ? (int)((const long long*)labels)[cell]
                      : ((const int*)labels)[cell];
        if (g < 0) g = 0;
        float xx = logits[cell * LL + tid];
        float m0 = __shfl_sync(FULL, xx, 0);
        float cand = (xx - m0) + (tid == g ? 0.0f : 1.0f)
                               + (tid == 0 ? NEGV : 0.0f);
#pragma unroll
        for (int o = 16; o > 0; o >>= 1)
            cand = fmaxf(cand, __shfl_xor_sync(FULL, cand, o));
        if (tid == 0) potS[jj] = cand;          // potS[0][len-1]
    }
    __syncthreads();

    // ---- width 0 ----
    if (tid < NN_) {
        float tv = potS[tid * PSP];
        A[tid * PA]            = tv;            // beta(i,0)
        Bend[tid * PBE + 127]  = tv;            // ends at i, width 0
    }
    __syncthreads();

    // ---- tile loop ----
    for (int W = 0; W < NN_; W += TT) {
        // Bulk (no syncs, reads only pre-tile data; pads are NEG -> auto-masked)
        if (rb * 8 <= 126 - W) {
            const float* ap = A + i * PA;
            const float* b0 = Bend + (i + W + sg + 1) * PBE + (127 - W - sg); // s=sg+1
            const float* b1 = Bend + (i + W + sg + 5) * PBE + (123 - W - sg); // s=sg+5
            float acc0 = NEGV, acc1 = NEGV;
#pragma unroll 4
            for (int k = 0; k <= W; ++k) {
                float a = ap[k];
                acc0 = fmaxf(acc0, a + b0[k]);
                acc1 = fmaxf(acc1, a + b1[k]);
            }
            Pt[i * PT + sg + 1] = acc0;
            Pt[i * PT + sg + 5] = acc1;
        }
        __syncthreads();

        // Fixup: warps 0-3 only; one row per lane; named barrier between s-steps
        if (tid < 128) {
            const int r = tid;
            const float* Ar = A + r * PA;
#pragma unroll
            for (int s = 1; s <= TT; ++s) {
                const int w = W + s;
                if (r <= 127 - w) {
                    float m = Pt[r * PT + s];
#pragma unroll
                    for (int t = 0; t < s - 1; ++t) {
                        // k = t: small-old left + large-new right (row r+t+1)
                        m = fmaxf(m, Ar[t] + A[(r + t + 1) * PA + (w - 1 - t)]);
                        // k = w-1-t: large-new left (own row) + small-old right
                        m = fmaxf(m, Ar[w - 1 - t] + A[(r + w - t) * PA + t]);
                    }
                    float nv = m + potS[r * PSP + w];
                    A[r * PA + w]               = nv;
                    Bend[(r + w) * PBE + 127 - w] = nv;
                }
                if (s < TT) asm volatile("bar.sync 1, 128;" ::: "memory");
            }
        }
        __syncthreads();
    }

    // ---- margin + deterministic final reduce ----
    if (tid == 0) {
        float gold = 0.0f;
#pragma unroll
        for (int t = 0; t < PARTS; ++t) gold += red[t];   // fixed order
        float pred = A[len - 1];                           // beta(0, len-1)
        g_margin[b] = fmaxf(pred - gold, 0.0f);
        __threadfence();
        unsigned old = atomicInc(&g_count, BB - 1);        // wraps -> replay/graph-safe
        if (old == BB - 1) {                               // last block: fixed-order mean
            float s = 0.0f;
            volatile float* gm = g_margin;
#pragma unroll
            for (int t = 0; t < BB; ++t) s += gm[t];
            out[0] = s * (1.0f / (float)BB);
        }
    }
}

// ---------------- launch ----------------
extern "C" void kernel_launch(void* const* d_in, const int* in_sizes, int n_in,
                              void* d_out, int out_size) {
    const float* logits = (const float*)d_in[0];
    const void*  labels = d_in[1];

    const int smem_floats = AROWS * PA + BEROWS * PBE + NN_ * PSP + PTROWS * PT;
    const int smem_bytes  = smem_floats * (int)sizeof(float);   // ~220 KB
    cudaFuncSetAttribute(k2_cky, cudaFuncAttributeMaxDynamicSharedMemorySize, smem_bytes);

    k1_pot<<<K1_BLOCKS, 256>>>(logits, labels);
    k2_cky<<<BB, 512, smem_bytes>>>(logits, labels, (float*)d_out);
}